// round 7
// baseline (speedup 1.0000x reference)
#include <cuda_runtime.h>
#include <cuda_fp16.h>
#include <math.h>
#include <stdint.h>

// ---------------------------------------------------------------------------
// AuxLossFreeGate: scores = sigmoid(x @ W^T), group-limited top-k gate.
// GEMM: warp mma.sync fp16, 2-way RN split (x = x1 + x2*2^-12, same for w),
// 3 product planes. W is pre-split ONCE per launch into a device-global image
// laid out exactly as the GEMM's SMEM B region -> hot loop copies it with
// cp.async (no W convert ALU in the GEMM).
// Gate: lane-owns-8-consecutive-experts layout, coalesced loads, parallel
// group top-2, rank-based group top-4, key-packed top-8.
// ---------------------------------------------------------------------------

#define N_EXPERTS   256
#define DIM_K       2048
#define N_GROUPS    8
#define EPG         32
#define TOPK        8
#define TOPK_GROUPS 4
#define ROUTE_SCALE 2.5f
#define MAX_T       32768
#define NEG_INF_F   (-1e30f)

__device__ float g_scores[(size_t)MAX_T * N_EXPERTS];

// ---------------- GEMM config ----------------
#define KC      32
#define NCHUNK  (DIM_K / KC)
#define ABLK    144
#define APLANE  (16 * ABLK)              // 2304 u32 per A plane
#define BBLK    66
#define BPLANE  (32 * BBLK)              // 2112 u32 per B plane
#define SB_OFF  (2 * APLANE)             // 4608
#define BCHUNK  (2 * BPLANE)             // 4224 u32 per (nh, chunk) image
#define SMEM_U32 (SB_OFF + BCHUNK)       // 8832 u32 per buffer
#define SMEM_BYTES (2 * SMEM_U32 * 4)    // ~69 KB double buffered

// W image: [nh(2)][chunk(64)][plane(2)][2112], exact SMEM B layout.
__device__ __align__(16) uint32_t g_wimg[2 * NCHUNK * BCHUNK];

#define MMA_F16(d, a, b) asm volatile( \
    "mma.sync.aligned.m16n8k16.row.col.f32.f16.f16.f32 " \
    "{%0,%1,%2,%3},{%4,%5,%6,%7},{%8,%9},{%0,%1,%2,%3};" \
    : "+f"((d)[0]), "+f"((d)[1]), "+f"((d)[2]), "+f"((d)[3]) \
    : "r"((a).x), "r"((a).y), "r"((a).z), "r"((a).w), "r"((b).x), "r"((b).y))

#define CP_ASYNC16(dst_u32, src_ptr) \
    asm volatile("cp.async.cg.shared.global [%0], [%1], 16;" \
                 :: "r"(dst_u32), "l"(src_ptr) : "memory")
#define CP_COMMIT()  asm volatile("cp.async.commit_group;" ::: "memory")
#define CP_WAIT0()   asm volatile("cp.async.wait_group 0;" ::: "memory")

__device__ __forceinline__ uint32_t smem_to_u32(const void* p) {
    uint32_t a;
    asm("{ .reg .u64 t; cvta.to.shared.u64 t, %1; cvt.u32.u64 %0, t; }" : "=r"(a) : "l"(p));
    return a;
}

// 2-way fp16 split of 4 floats, pairwise packed (even k in lo half).
__device__ __forceinline__ void hsplit4(float4 v, uint32_t p1[2], uint32_t p2[2])
{
    __half2 a1 = __floats2half2_rn(v.x, v.y);
    __half2 b1 = __floats2half2_rn(v.z, v.w);
    p1[0] = *(uint32_t*)&a1;
    p1[1] = *(uint32_t*)&b1;
    float rx = (v.x - __half2float(__low2half(a1)))  * 4096.0f;
    float ry = (v.y - __half2float(__high2half(a1))) * 4096.0f;
    float rz = (v.z - __half2float(__low2half(b1)))  * 4096.0f;
    float rw = (v.w - __half2float(__high2half(b1))) * 4096.0f;
    __half2 a2 = __floats2half2_rn(rx, ry);
    __half2 b2 = __floats2half2_rn(rz, rw);
    p2[0] = *(uint32_t*)&a2;
    p2[1] = *(uint32_t*)&b2;
}

__device__ __forceinline__ float sigf(float v) { return 1.0f / (1.0f + expf(-v)); }

// ---------------------------------------------------------------------------
// Kernel 0: pre-split W into fragment-image layout. One thread per k-pair.
// ---------------------------------------------------------------------------
__global__ __launch_bounds__(256)
void wsplit_kernel(const float* __restrict__ W)
{
    const int gid = blockIdx.x * 256 + threadIdx.x;   // 0 .. 256*1024-1
    const int n = gid >> 10;                          // expert row
    const int p = gid & 1023;                         // k-pair index
    const int k = 2 * p;

    float2 w = *(const float2*)(W + (size_t)n * DIM_K + k);
    uint32_t p1[2], p2[2];
    hsplit4(make_float4(w.x, w.y, 0.f, 0.f), p1, p2);  // only .x/.y lanes used

    const int nh = n >> 7;
    const int nl = n & 127;
    const int nt = nl >> 3;
    const int cn = nl & 7;
    const int c  = k >> 5;
    const int kk = k & 31;
    const int ks = kk >> 4;
    const int kb = kk & 15;                     // even
    const int slot = cn * 4 + ((kb >> 1) & 3);
    const int reg  = kb >> 3;

    const int base = (nh * NCHUNK + c) * BCHUNK + (nt * 2 + ks) * BBLK + slot * 2 + reg;
    g_wimg[base]          = p1[0];
    g_wimg[base + BPLANE] = p2[0];
}

// ---------------------------------------------------------------------------
// Kernel 1: GEMM. CTA = 128 tokens x 128 experts, 8 warps (4M x 2N).
// ---------------------------------------------------------------------------
__global__ __launch_bounds__(256)
void gemm_hmma_kernel(const float* __restrict__ X)
{
    extern __shared__ uint32_t sm[];
    const uint32_t smem_base = smem_to_u32(sm);
    const int tid  = threadIdx.x;
    const int warp = tid >> 5;
    const int lane = tid & 31;

    const int mt_blk = blockIdx.x >> 1;
    const int nh     = blockIdx.x & 1;

    const float* xb = X + (size_t)mt_blk * 128 * DIM_K;
    const uint32_t* wimg = g_wimg + (size_t)nh * NCHUNK * BCHUNK;

    // A loader geometry (identical to proven round-6 formulas)
    int goff[4], aad[4];
#pragma unroll
    for (int j = 0; j < 4; ++j) {
        const int idx = tid + j * 256;
        const int row = idx >> 3;
        const int c4  = (idx & 7) * 4;
        goff[j] = row * DIM_K + c4;
        const int ks = c4 >> 4;
        const int kb = c4 & 15;
        const int tc = (kb >> 1) & 3;
        const int mt = row >> 4, r = row & 15;
        const int slot = (r & 7) * 4 + tc;
        const int reg  = (r >> 3) + 2 * ((kb >> 3) & 1);
        aad[j] = (mt * 2 + ks) * ABLK + slot * 4 + (slot >> 3) * 4 + reg;
    }

    float accM[2][8][4], accS[2][8][4];
#pragma unroll
    for (int mi = 0; mi < 2; ++mi)
#pragma unroll
        for (int ni = 0; ni < 8; ++ni)
#pragma unroll
            for (int q = 0; q < 4; ++q) { accM[mi][ni][q] = 0.f; accS[mi][ni][q] = 0.f; }

    const int wmt = (warp >> 1) * 2;
    const int wnt = (warp & 1) * 8;

    // prologue: issue B(0) copy, load A(0)
    {
        const uint32_t* src = wimg;                          // chunk 0
        const uint32_t dstb = smem_base + (SB_OFF + 0) * 4;  // buf0 B region
#pragma unroll
        for (int j = 0; j < 4; ++j) {
            const int idx = j * 256 + tid;                   // uint4 index
            CP_ASYNC16(dstb + idx * 16, src + idx * 4);
        }
        if (tid < 32) {
            const int idx = 1024 + tid;
            CP_ASYNC16(dstb + idx * 16, src + idx * 4);
        }
        CP_COMMIT();
    }
    float4 ra[4];
#pragma unroll
    for (int j = 0; j < 4; ++j) ra[j] = *(const float4*)(xb + goff[j]);

    for (int c = 0; c < NCHUNK; ++c) {
        uint32_t* smb = sm + (c & 1) * SMEM_U32;

        // ---- split + store A(c) ----
#pragma unroll
        for (int j = 0; j < 4; ++j) {
            uint32_t p1[2], p2[2];
            hsplit4(ra[j], p1, p2);
            smb[aad[j]]              = p1[0];
            smb[aad[j] + 4]          = p1[1];
            smb[aad[j] + APLANE]     = p2[0];
            smb[aad[j] + APLANE + 4] = p2[1];
        }

        // ---- wait B(c), sync ----
        CP_WAIT0();
        __syncthreads();

        // ---- issue B(c+1) (targets buffer no warp is reading now) ----
        if (c + 1 < NCHUNK) {
            const uint32_t* src = wimg + (c + 1) * BCHUNK;
            const uint32_t dstb = smem_base + (((c + 1) & 1) * SMEM_U32 + SB_OFF) * 4;
#pragma unroll
            for (int j = 0; j < 4; ++j) {
                const int idx = j * 256 + tid;
                CP_ASYNC16(dstb + idx * 16, src + idx * 4);
            }
            if (tid < 32) {
                const int idx = 1024 + tid;
                CP_ASYNC16(dstb + idx * 16, src + idx * 4);
            }
        }
        CP_COMMIT();   // uniform group count every iteration

        // ---- prefetch A(c+1) ----
        if (c + 1 < NCHUNK) {
            const int k0 = (c + 1) * KC;
#pragma unroll
            for (int j = 0; j < 4; ++j)
                ra[j] = *(const float4*)(xb + goff[j] + k0);
        }

        // ---- compute chunk c: 3 planes ----
#pragma unroll
        for (int ks = 0; ks < 2; ++ks) {
            uint4 af[2][2];
#pragma unroll
            for (int p = 0; p < 2; ++p)
#pragma unroll
                for (int mi = 0; mi < 2; ++mi)
                    af[p][mi] = *(const uint4*)&smb[p * APLANE +
                        ((wmt + mi) * 2 + ks) * ABLK + lane * 4 + (lane >> 3) * 4];

#pragma unroll
            for (int nq = 0; nq < 2; ++nq) {
                const int nb = nq * 4;
                uint2 bf[4][2];
#pragma unroll
                for (int ni4 = 0; ni4 < 4; ++ni4) {
                    const int bbase = ((wnt + nb + ni4) * 2 + ks) * BBLK + lane * 2;
#pragma unroll
                    for (int q = 0; q < 2; ++q)
                        bf[ni4][q] = *(const uint2*)&smb[SB_OFF + q * BPLANE + bbase];
                }
#define DO_TERM(DST, P_, Q_) \
                { \
                    _Pragma("unroll") \
                    for (int ni4 = 0; ni4 < 4; ++ni4) { \
                        MMA_F16(DST[0][nb + ni4], af[P_][0], bf[ni4][Q_]); \
                        MMA_F16(DST[1][nb + ni4], af[P_][1], bf[ni4][Q_]); \
                    } \
                }
                DO_TERM(accM, 0, 0)
                DO_TERM(accS, 0, 1)
                DO_TERM(accS, 1, 0)
#undef DO_TERM
            }
        }
    }

    // ---- epilogue: accM + accS*2^-12 -> sigmoid -> g_scores ----
    const float INV = 1.0f / 4096.0f;
    const int rbase = mt_blk * 128 + (warp >> 1) * 32 + (lane >> 2);
    const int cbase = nh * 128 + (warp & 1) * 64 + (lane & 3) * 2;
#pragma unroll
    for (int mi = 0; mi < 2; ++mi) {
#pragma unroll
        for (int ni = 0; ni < 8; ++ni) {
            const int rr = rbase + mi * 16;
            const int cc = cbase + ni * 8;
            float2 v0, v1;
            v0.x = sigf(fmaf(accS[mi][ni][0], INV, accM[mi][ni][0]));
            v0.y = sigf(fmaf(accS[mi][ni][1], INV, accM[mi][ni][1]));
            v1.x = sigf(fmaf(accS[mi][ni][2], INV, accM[mi][ni][2]));
            v1.y = sigf(fmaf(accS[mi][ni][3], INV, accM[mi][ni][3]));
            *(float2*)&g_scores[(size_t)rr * N_EXPERTS + cc] = v0;
            *(float2*)&g_scores[(size_t)(rr + 8) * N_EXPERTS + cc] = v1;
        }
    }
}

// ---------------------------------------------------------------------------
// Kernel 2: gating. One warp per token; lane owns experts [lane*8, lane*8+8).
// ---------------------------------------------------------------------------
__device__ __forceinline__ uint32_t fkey(float f) {
    uint32_t u = __float_as_uint(f);
    return u ^ (uint32_t)(((int32_t)u >> 31) | 0x80000000);
}

__global__ __launch_bounds__(256)
void gate_kernel(const float* __restrict__ bias,
                 float* __restrict__ out_w, float* __restrict__ out_i, int T)
{
    const int warp = threadIdx.x >> 5;
    const int lane = threadIdx.x & 31;
    const int t = blockIdx.x * 8 + warp;
    if (t >= T) return;

    const float* srow = g_scores + (size_t)t * N_EXPERTS;

    // coalesced loads: lane reads its 8 consecutive experts
    float s[8], b[8];
    {
        float4 s0 = *(const float4*)(srow + lane * 8);
        float4 s1 = *(const float4*)(srow + lane * 8 + 4);
        float4 b0 = *(const float4*)(bias + lane * 8);
        float4 b1 = *(const float4*)(bias + lane * 8 + 4);
        s[0]=s0.x; s[1]=s0.y; s[2]=s0.z; s[3]=s0.w;
        s[4]=s1.x; s[5]=s1.y; s[6]=s1.z; s[7]=s1.w;
        b[0]=s[0]+b0.x; b[1]=s[1]+b0.y; b[2]=s[2]+b0.z; b[3]=s[3]+b0.w;
        b[4]=s[4]+b1.x; b[5]=s[5]+b1.y; b[6]=s[6]+b1.z; b[7]=s[7]+b1.w;
    }

    // local top-2 of this lane's 8 biased scores
    float m1 = NEG_INF_F, m2 = NEG_INF_F;
#pragma unroll
    for (int j = 0; j < 8; ++j) {
        float v = b[j];
        if (v > m1) { m2 = m1; m1 = v; }
        else if (v > m2) { m2 = v; }
    }
    // merge across the 4 lanes of this group (lanes 4g..4g+3)
#pragma unroll
    for (int off = 1; off <= 2; off <<= 1) {
        float o1 = __shfl_xor_sync(0xffffffffu, m1, off);
        float o2 = __shfl_xor_sync(0xffffffffu, m2, off);
        if (o1 > m1) { m2 = fmaxf(m1, o2); m1 = o1; }
        else         { m2 = fmaxf(m2, o1); }
    }
    const float gsc = m1 + m2;          // group score (same across quad)
    const int myg = lane >> 2;

    // rank of my group among 8 (ties -> lower group index wins)
    int rank = 0;
#pragma unroll
    for (int g2 = 0; g2 < N_GROUPS; ++g2) {
        float og = __shfl_sync(0xffffffffu, gsc, g2 * 4);
        rank += (og > gsc) || (og == gsc && g2 < myg);
    }
    const bool kept = rank < TOPK_GROUPS;

    // sortable keys; dead lanes use mask=0
    uint32_t key[8];
#pragma unroll
    for (int j = 0; j < 8; ++j) key[j] = fkey(b[j]);
    uint32_t mask = kept ? 0xFFu : 0u;

    float topw[TOPK]; int topi[TOPK];
    float wsum = 0.f;
#pragma unroll
    for (int it = 0; it < TOPK; ++it) {
        uint32_t bk = 0; uint32_t be = 0x7fffffffu; float bs = 0.f;
#pragma unroll
        for (int j = 0; j < 8; ++j) {
            const bool live = (mask >> j) & 1u;
            if (live && key[j] > bk) { bk = key[j]; be = lane * 8 + j; bs = s[j]; }
        }
        // warp argmax on key; tie -> smaller expert index
#pragma unroll
        for (int off = 16; off; off >>= 1) {
            uint32_t ok = __shfl_xor_sync(0xffffffffu, bk, off);
            uint32_t oe = __shfl_xor_sync(0xffffffffu, be, off);
            float    os = __shfl_xor_sync(0xffffffffu, bs, off);
            if (ok > bk || (ok == bk && oe < be)) { bk = ok; be = oe; bs = os; }
        }
        topw[it] = bs; topi[it] = (int)be; wsum += bs;
        if ((be >> 3) == (uint32_t)lane) mask &= ~(1u << (be & 7u));
    }

    const float scale = ROUTE_SCALE / fmaxf(wsum, 1e-10f);
    if (lane == 0) {
#pragma unroll
        for (int j = 0; j < TOPK; ++j) {
            out_w[(size_t)t * TOPK + j] = topw[j] * scale;
            out_i[(size_t)t * TOPK + j] = (float)topi[j];
        }
    }
}

// ---------------------------------------------------------------------------
extern "C" void kernel_launch(void* const* d_in, const int* in_sizes, int n_in,
                              void* d_out, int out_size)
{
    const float* x    = (const float*)d_in[0];
    const float* w    = (const float*)d_in[1];
    const float* bias = (const float*)d_in[2];

    int T = in_sizes[0] / DIM_K;
    if (T > MAX_T) T = MAX_T;

    float* out_w = (float*)d_out;
    float* out_i = (float*)d_out + (size_t)T * TOPK;

    wsplit_kernel<<<1024, 256>>>(w);

    cudaFuncSetAttribute(gemm_hmma_kernel,
                         cudaFuncAttributeMaxDynamicSharedMemorySize, SMEM_BYTES);
    gemm_hmma_kernel<<<(T / 128) * 2, 256, SMEM_BYTES>>>(x);

    gate_kernel<<<(T + 7) / 8, 256>>>(bias, out_w, out_i, T);
}